// round 1
// baseline (speedup 1.0000x reference)
#include <cuda_runtime.h>
#include <math.h>
#include <stdint.h>

// ---------------------------------------------------------------------------
// MSEObserver: 100-candidate symmetric-threshold grid search, Lp loss p=2.4.
// Strategy: exact min/max pass, then a 256K-bin signed histogram of x, then
// score all 100 candidates from the histogram (26M evals instead of 2.57G),
// then argmin with reference tie-breaking (strict <, ascending i).
// ---------------------------------------------------------------------------

#define NBINS (1 << 18)   // 262144 bins, 1 MB of uint32 counts (L2-resident)
#define NUM_T 100

__device__ unsigned int g_min_enc;
__device__ unsigned int g_max_enc;
__device__ unsigned int g_hist[NBINS];
__device__ double       g_scores[NUM_T];

// Order-preserving float <-> uint encoding (monotonic increasing).
__device__ __forceinline__ unsigned int enc_f(float f) {
    unsigned int u = __float_as_uint(f);
    return (u & 0x80000000u) ? ~u : (u | 0x80000000u);
}
__device__ __forceinline__ float dec_f(unsigned int u) {
    u = (u & 0x80000000u) ? (u & 0x7fffffffu) : ~u;
    return __uint_as_float(u);
}

// ---------------------------------------------------------------------------
// K0: reset all device-global scratch (graph replays must be deterministic).
// ---------------------------------------------------------------------------
__global__ void k_init() {
    int idx = blockIdx.x * blockDim.x + threadIdx.x;
    if (idx < NBINS) g_hist[idx] = 0u;
    if (idx == 0) { g_min_enc = 0xFFFFFFFFu; g_max_enc = 0u; }
    if (idx < NUM_T) g_scores[idx] = 0.0;
}

// ---------------------------------------------------------------------------
// K1: global min/max (float4 grid-stride, warp+block reduce, 1 atomic/block).
// ---------------------------------------------------------------------------
__global__ void __launch_bounds__(256) k_minmax(const float* __restrict__ x, int n) {
    const int n4 = n >> 2;
    const float4* __restrict__ x4 = (const float4*)x;

    float lmin =  INFINITY;
    float lmax = -INFINITY;

    for (int i = blockIdx.x * blockDim.x + threadIdx.x; i < n4;
         i += gridDim.x * blockDim.x) {
        float4 v = x4[i];
        lmin = fminf(lmin, fminf(fminf(v.x, v.y), fminf(v.z, v.w)));
        lmax = fmaxf(lmax, fmaxf(fmaxf(v.x, v.y), fmaxf(v.z, v.w)));
    }
    // tail (n not multiple of 4)
    if (blockIdx.x == 0) {
        int t = n4 * 4 + threadIdx.x;
        if (t < n) { float v = x[t]; lmin = fminf(lmin, v); lmax = fmaxf(lmax, v); }
    }

    // warp reduce
    for (int o = 16; o > 0; o >>= 1) {
        lmin = fminf(lmin, __shfl_xor_sync(0xffffffffu, lmin, o));
        lmax = fmaxf(lmax, __shfl_xor_sync(0xffffffffu, lmax, o));
    }
    __shared__ float smin[8], smax[8];
    int wid = threadIdx.x >> 5, lid = threadIdx.x & 31;
    if (lid == 0) { smin[wid] = lmin; smax[wid] = lmax; }
    __syncthreads();
    if (wid == 0) {
        lmin = (lid < 8) ? smin[lid] :  INFINITY;
        lmax = (lid < 8) ? smax[lid] : -INFINITY;
        for (int o = 4; o > 0; o >>= 1) {
            lmin = fminf(lmin, __shfl_xor_sync(0xffffffffu, lmin, o));
            lmax = fmaxf(lmax, __shfl_xor_sync(0xffffffffu, lmax, o));
        }
        if (lid == 0) {
            atomicMin(&g_min_enc, enc_f(lmin));
            atomicMax(&g_max_enc, enc_f(lmax));
        }
    }
}

// ---------------------------------------------------------------------------
// K2: signed histogram of x over [-xrange, xrange].
// ---------------------------------------------------------------------------
__global__ void __launch_bounds__(256) k_hist(const float* __restrict__ x, int n) {
    const float xmin = dec_f(g_min_enc);
    const float xmax = dec_f(g_max_enc);
    const float xr   = fmaxf(fabsf(xmin), xmax);
    const float lo   = -xr;
    const float invw = (float)NBINS / (2.0f * xr);

    const int n4 = n >> 2;
    const float4* __restrict__ x4 = (const float4*)x;

    for (int i = blockIdx.x * blockDim.x + threadIdx.x; i < n4;
         i += gridDim.x * blockDim.x) {
        float4 v = x4[i];
        float vv[4] = {v.x, v.y, v.z, v.w};
        #pragma unroll
        for (int k = 0; k < 4; k++) {
            int b = (int)((vv[k] - lo) * invw);   // arg >= 0, cast == floor
            b = min(b, NBINS - 1);
            b = max(b, 0);
            atomicAdd(&g_hist[b], 1u);
        }
    }
    if (blockIdx.x == 0) {
        int t = n4 * 4 + threadIdx.x;
        if (t < n) {
            int b = (int)((x[t] - lo) * invw);
            b = min(b, NBINS - 1);
            b = max(b, 0);
            atomicAdd(&g_hist[b], 1u);
        }
    }
}

// ---------------------------------------------------------------------------
// K3: one block per candidate i = blockIdx.x + 1. Score from histogram.
// score_i = sum_bins count * |c - clamp(round(c/scale),-128,127)*scale|^2.4
// Accumulate in double, block-reduce, deterministic single store.
// ---------------------------------------------------------------------------
__global__ void __launch_bounds__(256) k_scores() {
    const int i = blockIdx.x + 1;
    const float xmin = dec_f(g_min_enc);
    const float xmax = dec_f(g_max_enc);
    const float xr   = fmaxf(fabsf(xmin), xmax);

    const float thres = xr / 100.0f * (float)i;          // match ref fp32 order
    const float scale = fmaxf(thres / 127.5f, 1e-8f);
    const float inv_scale = 1.0f / scale;

    const double lo_d = -(double)xr;
    const double w_d  = 2.0 * (double)xr / (double)NBINS;

    double acc = 0.0;
    for (int b = threadIdx.x; b < NBINS; b += blockDim.x) {
        unsigned int cnt = g_hist[b];
        if (cnt == 0u) continue;
        float c = (float)(lo_d + ((double)b + 0.5) * w_d);   // bin center
        float t = c * inv_scale;
        float r = rintf(t);                                   // round half-even
        r = fminf(fmaxf(r, -128.0f), 127.0f);                 // clip
        float e = fabsf(fmaf(-r, scale, c));                  // |c - r*scale|
        float p = (e > 0.0f) ? exp2f(2.4f * __log2f(e)) : 0.0f;  // e^2.4
        acc += (double)cnt * (double)p;
    }

    __shared__ double sacc[256];
    sacc[threadIdx.x] = acc;
    __syncthreads();
    for (int s = 128; s > 0; s >>= 1) {
        if (threadIdx.x < s) sacc[threadIdx.x] += sacc[threadIdx.x + s];
        __syncthreads();
    }
    if (threadIdx.x == 0) g_scores[blockIdx.x] = sacc[0];
}

// ---------------------------------------------------------------------------
// K4: argmin (strict <, ascending i, matching jax.lax.scan order) -> output.
// ---------------------------------------------------------------------------
__global__ void k_argmin(float* __restrict__ out) {
    if (threadIdx.x == 0 && blockIdx.x == 0) {
        const float xmin = dec_f(g_min_enc);
        const float xmax = dec_f(g_max_enc);
        const float xr   = fmaxf(fabsf(xmin), xmax);

        double best = 1e300;
        int bi = 1;
        #pragma unroll 1
        for (int i = 1; i <= NUM_T; i++) {
            double s = g_scores[i - 1];
            if (s < best) { best = s; bi = i; }
        }
        float thres = xr / 100.0f * (float)bi;
        out[0] = -thres;
        out[1] =  thres;
    }
}

// ---------------------------------------------------------------------------
// Launch: 5 kernels on the default stream (graph-capturable, no allocs).
// ---------------------------------------------------------------------------
extern "C" void kernel_launch(void* const* d_in, const int* in_sizes, int n_in,
                              void* d_out, int out_size) {
    const float* x = (const float*)d_in[0];
    const int n = in_sizes[0];

    k_init<<<(NBINS + 255) / 256, 256>>>();
    k_minmax<<<1184, 256>>>(x, n);
    k_hist<<<1184, 256>>>(x, n);
    k_scores<<<NUM_T, 256>>>();
    k_argmin<<<1, 32>>>((float*)d_out);
}

// round 2
// speedup vs baseline: 1.3927x; 1.3927x over previous
#include <cuda_runtime.h>
#include <math.h>
#include <stdint.h>

// ---------------------------------------------------------------------------
// MSEObserver: 100-candidate symmetric-threshold grid search, Lp loss p=2.4.
// R2: NBINS 256K -> 32K (64x fewer MUFU evals in k_scores, which was measured
// at its MUFU roofline), chunked k_scores grid for occupancy, all-fp32 inner
// loop with Kahan accumulation, deterministic fixed-order partial reduction.
// ---------------------------------------------------------------------------

#define NBINS 32768
#define NUM_T 100
#define NCHUNK 8
#define BINS_PER_CHUNK (NBINS / NCHUNK)   // 4096

__device__ unsigned int g_min_enc;
__device__ unsigned int g_max_enc;
__device__ unsigned int g_hist[NBINS];
__device__ double       g_partial[NUM_T][NCHUNK];

// Order-preserving float <-> uint encoding (monotonic increasing).
__device__ __forceinline__ unsigned int enc_f(float f) {
    unsigned int u = __float_as_uint(f);
    return (u & 0x80000000u) ? ~u : (u | 0x80000000u);
}
__device__ __forceinline__ float dec_f(unsigned int u) {
    u = (u & 0x80000000u) ? (u & 0x7fffffffu) : ~u;
    return __uint_as_float(u);
}

// ---------------------------------------------------------------------------
// K0: reset all device-global scratch (graph replays must be deterministic).
// ---------------------------------------------------------------------------
__global__ void k_init() {
    int idx = blockIdx.x * blockDim.x + threadIdx.x;
    if (idx < NBINS) g_hist[idx] = 0u;
    if (idx == 0) { g_min_enc = 0xFFFFFFFFu; g_max_enc = 0u; }
    if (idx < NUM_T * NCHUNK) ((double*)g_partial)[idx] = 0.0;
}

// ---------------------------------------------------------------------------
// K1: global min/max (float4 grid-stride, warp+block reduce, 1 atomic/block).
// ---------------------------------------------------------------------------
__global__ void __launch_bounds__(256) k_minmax(const float* __restrict__ x, int n) {
    const int n4 = n >> 2;
    const float4* __restrict__ x4 = (const float4*)x;

    float lmin =  INFINITY;
    float lmax = -INFINITY;

    for (int i = blockIdx.x * blockDim.x + threadIdx.x; i < n4;
         i += gridDim.x * blockDim.x) {
        float4 v = x4[i];
        lmin = fminf(lmin, fminf(fminf(v.x, v.y), fminf(v.z, v.w)));
        lmax = fmaxf(lmax, fmaxf(fmaxf(v.x, v.y), fmaxf(v.z, v.w)));
    }
    // tail (n not multiple of 4)
    if (blockIdx.x == 0) {
        int t = n4 * 4 + threadIdx.x;
        if (t < n) { float v = x[t]; lmin = fminf(lmin, v); lmax = fmaxf(lmax, v); }
    }

    // warp reduce
    for (int o = 16; o > 0; o >>= 1) {
        lmin = fminf(lmin, __shfl_xor_sync(0xffffffffu, lmin, o));
        lmax = fmaxf(lmax, __shfl_xor_sync(0xffffffffu, lmax, o));
    }
    __shared__ float smin[8], smax[8];
    int wid = threadIdx.x >> 5, lid = threadIdx.x & 31;
    if (lid == 0) { smin[wid] = lmin; smax[wid] = lmax; }
    __syncthreads();
    if (wid == 0) {
        lmin = (lid < 8) ? smin[lid] :  INFINITY;
        lmax = (lid < 8) ? smax[lid] : -INFINITY;
        for (int o = 4; o > 0; o >>= 1) {
            lmin = fminf(lmin, __shfl_xor_sync(0xffffffffu, lmin, o));
            lmax = fmaxf(lmax, __shfl_xor_sync(0xffffffffu, lmax, o));
        }
        if (lid == 0) {
            atomicMin(&g_min_enc, enc_f(lmin));
            atomicMax(&g_max_enc, enc_f(lmax));
        }
    }
}

// ---------------------------------------------------------------------------
// K2: signed histogram of x over [-xrange, xrange].
// ---------------------------------------------------------------------------
__global__ void __launch_bounds__(256) k_hist(const float* __restrict__ x, int n) {
    const float xmin = dec_f(g_min_enc);
    const float xmax = dec_f(g_max_enc);
    const float xr   = fmaxf(fabsf(xmin), xmax);
    const float lo   = -xr;
    const float invw = (float)NBINS / (2.0f * xr);

    const int n4 = n >> 2;
    const float4* __restrict__ x4 = (const float4*)x;

    for (int i = blockIdx.x * blockDim.x + threadIdx.x; i < n4;
         i += gridDim.x * blockDim.x) {
        float4 v = x4[i];
        float vv[4] = {v.x, v.y, v.z, v.w};
        #pragma unroll
        for (int k = 0; k < 4; k++) {
            int b = (int)((vv[k] - lo) * invw);   // arg >= 0, cast == floor
            b = min(b, NBINS - 1);
            b = max(b, 0);
            atomicAdd(&g_hist[b], 1u);
        }
    }
    if (blockIdx.x == 0) {
        int t = n4 * 4 + threadIdx.x;
        if (t < n) {
            int b = (int)((x[t] - lo) * invw);
            b = min(b, NBINS - 1);
            b = max(b, 0);
            atomicAdd(&g_hist[b], 1u);
        }
    }
}

// ---------------------------------------------------------------------------
// K3: grid (NUM_T, NCHUNK). Block (i, c) scores candidate i+1 over bin chunk c.
// score contribution = sum_bins count * |ctr - clamp(rint(ctr/scale))*scale|^2.4
// fp32 inner loop + Kahan per thread; double block reduce; deterministic store.
// ---------------------------------------------------------------------------
__global__ void __launch_bounds__(256) k_scores() {
    const int i     = blockIdx.x + 1;
    const int chunk = blockIdx.y;

    const float xmin = dec_f(g_min_enc);
    const float xmax = dec_f(g_max_enc);
    const float xr   = fmaxf(fabsf(xmin), xmax);

    const float thres = xr / 100.0f * (float)i;          // match ref fp32 order
    const float scale = fmaxf(thres / 127.5f, 1e-8f);
    const float inv_scale = 1.0f / scale;

    const float lo = -xr;
    const float w  = 2.0f * xr / (float)NBINS;

    float acc = 0.0f, comp = 0.0f;                        // Kahan
    const int b_end = (chunk + 1) * BINS_PER_CHUNK;
    for (int b = chunk * BINS_PER_CHUNK + threadIdx.x; b < b_end; b += 256) {
        unsigned int cnt = g_hist[b];
        if (cnt == 0u) continue;
        float c = fmaf((float)b + 0.5f, w, lo);           // bin center
        float t = c * inv_scale;
        float r = rintf(t);                               // round half-even
        r = fminf(fmaxf(r, -128.0f), 127.0f);             // clip
        float e = fabsf(fmaf(-r, scale, c));              // |c - r*scale|
        float p = exp2f(2.4f * __log2f(e));               // e^2.4 (e=0 -> 0)
        float term = (float)cnt * p;
        float y = term - comp;
        float s = acc + y;
        comp = (s - acc) - y;
        acc = s;
    }

    __shared__ double sacc[256];
    sacc[threadIdx.x] = (double)acc;
    __syncthreads();
    for (int s = 128; s > 0; s >>= 1) {
        if (threadIdx.x < s) sacc[threadIdx.x] += sacc[threadIdx.x + s];
        __syncthreads();
    }
    if (threadIdx.x == 0) g_partial[blockIdx.x][chunk] = sacc[0];
}

// ---------------------------------------------------------------------------
// K4: fixed-order chunk sums, argmin (strict <, ascending i) -> output.
// ---------------------------------------------------------------------------
__global__ void k_argmin(float* __restrict__ out) {
    if (threadIdx.x == 0 && blockIdx.x == 0) {
        const float xmin = dec_f(g_min_enc);
        const float xmax = dec_f(g_max_enc);
        const float xr   = fmaxf(fabsf(xmin), xmax);

        double best = 1e300;
        int bi = 1;
        #pragma unroll 1
        for (int i = 1; i <= NUM_T; i++) {
            double s = 0.0;
            #pragma unroll
            for (int c = 0; c < NCHUNK; c++) s += g_partial[i - 1][c];
            if (s < best) { best = s; bi = i; }
        }
        float thres = xr / 100.0f * (float)bi;
        out[0] = -thres;
        out[1] =  thres;
    }
}

// ---------------------------------------------------------------------------
// Launch: 5 kernels on the default stream (graph-capturable, no allocs).
// ---------------------------------------------------------------------------
extern "C" void kernel_launch(void* const* d_in, const int* in_sizes, int n_in,
                              void* d_out, int out_size) {
    const float* x = (const float*)d_in[0];
    const int n = in_sizes[0];

    k_init<<<(NBINS + 255) / 256, 256>>>();
    k_minmax<<<1184, 256>>>(x, n);
    k_hist<<<1184, 256>>>(x, n);
    dim3 sg(NUM_T, NCHUNK);
    k_scores<<<sg, 256>>>();
    k_argmin<<<1, 32>>>((float*)d_out);
}

// round 3
// speedup vs baseline: 2.4741x; 1.7765x over previous
#include <cuda_runtime.h>
#include <math.h>
#include <stdint.h>

// ---------------------------------------------------------------------------
// MSEObserver: 100-candidate symmetric-threshold grid search, Lp loss p=2.4.
// R3: decouple histogram resolution (256K bins -> low L2 atomic contention,
// ~435 max counts/bin) from scoring resolution (32K bins -> few MUFU evals).
// A collapse kernel sums groups of 8; since the grids nest exactly
// (b32 = b256 >> 3), scores are bitwise identical to R2's passing run.
// ---------------------------------------------------------------------------

#define NBINS_H (1 << 18)                  // 262144 histogram bins (1 MB)
#define NBINS_S (1 << 15)                  // 32768 scoring bins
#define COLLAPSE (NBINS_H / NBINS_S)       // 8
#define NUM_T 100
#define NCHUNK 8
#define BINS_PER_CHUNK (NBINS_S / NCHUNK)  // 4096

__device__ unsigned int g_min_enc;
__device__ unsigned int g_max_enc;
__device__ unsigned int g_hist[NBINS_H];
__device__ unsigned int g_hist_s[NBINS_S];
__device__ double       g_partial[NUM_T][NCHUNK];

// Order-preserving float <-> uint encoding (monotonic increasing).
__device__ __forceinline__ unsigned int enc_f(float f) {
    unsigned int u = __float_as_uint(f);
    return (u & 0x80000000u) ? ~u : (u | 0x80000000u);
}
__device__ __forceinline__ float dec_f(unsigned int u) {
    u = (u & 0x80000000u) ? (u & 0x7fffffffu) : ~u;
    return __uint_as_float(u);
}

// ---------------------------------------------------------------------------
// K0: reset all device-global scratch (graph replays must be deterministic).
// ---------------------------------------------------------------------------
__global__ void k_init() {
    int idx = blockIdx.x * blockDim.x + threadIdx.x;
    if (idx < NBINS_H) g_hist[idx] = 0u;
    if (idx == 0) { g_min_enc = 0xFFFFFFFFu; g_max_enc = 0u; }
    if (idx < NUM_T * NCHUNK) ((double*)g_partial)[idx] = 0.0;
}

// ---------------------------------------------------------------------------
// K1: global min/max (float4 grid-stride, warp+block reduce, 1 atomic/block).
// ---------------------------------------------------------------------------
__global__ void __launch_bounds__(256) k_minmax(const float* __restrict__ x, int n) {
    const int n4 = n >> 2;
    const float4* __restrict__ x4 = (const float4*)x;

    float lmin =  INFINITY;
    float lmax = -INFINITY;

    for (int i = blockIdx.x * blockDim.x + threadIdx.x; i < n4;
         i += gridDim.x * blockDim.x) {
        float4 v = x4[i];
        lmin = fminf(lmin, fminf(fminf(v.x, v.y), fminf(v.z, v.w)));
        lmax = fmaxf(lmax, fmaxf(fmaxf(v.x, v.y), fmaxf(v.z, v.w)));
    }
    // tail (n not multiple of 4)
    if (blockIdx.x == 0) {
        int t = n4 * 4 + threadIdx.x;
        if (t < n) { float v = x[t]; lmin = fminf(lmin, v); lmax = fmaxf(lmax, v); }
    }

    // warp reduce
    for (int o = 16; o > 0; o >>= 1) {
        lmin = fminf(lmin, __shfl_xor_sync(0xffffffffu, lmin, o));
        lmax = fmaxf(lmax, __shfl_xor_sync(0xffffffffu, lmax, o));
    }
    __shared__ float smin[8], smax[8];
    int wid = threadIdx.x >> 5, lid = threadIdx.x & 31;
    if (lid == 0) { smin[wid] = lmin; smax[wid] = lmax; }
    __syncthreads();
    if (wid == 0) {
        lmin = (lid < 8) ? smin[lid] :  INFINITY;
        lmax = (lid < 8) ? smax[lid] : -INFINITY;
        for (int o = 4; o > 0; o >>= 1) {
            lmin = fminf(lmin, __shfl_xor_sync(0xffffffffu, lmin, o));
            lmax = fmaxf(lmax, __shfl_xor_sync(0xffffffffu, lmax, o));
        }
        if (lid == 0) {
            atomicMin(&g_min_enc, enc_f(lmin));
            atomicMax(&g_max_enc, enc_f(lmax));
        }
    }
}

// ---------------------------------------------------------------------------
// K2: signed histogram of x over [-xrange, xrange] at 256K bins (low
// per-address contention: hottest bin ~435 counts for N(0,1) data).
// ---------------------------------------------------------------------------
__global__ void __launch_bounds__(256) k_hist(const float* __restrict__ x, int n) {
    const float xmin = dec_f(g_min_enc);
    const float xmax = dec_f(g_max_enc);
    const float xr   = fmaxf(fabsf(xmin), xmax);
    const float lo   = -xr;
    const float invw = (float)NBINS_H / (2.0f * xr);

    const int n4 = n >> 2;
    const float4* __restrict__ x4 = (const float4*)x;

    for (int i = blockIdx.x * blockDim.x + threadIdx.x; i < n4;
         i += gridDim.x * blockDim.x) {
        float4 v = x4[i];
        float vv[4] = {v.x, v.y, v.z, v.w};
        #pragma unroll
        for (int k = 0; k < 4; k++) {
            int b = (int)((vv[k] - lo) * invw);   // arg >= 0, cast == floor
            b = min(b, NBINS_H - 1);
            b = max(b, 0);
            atomicAdd(&g_hist[b], 1u);
        }
    }
    if (blockIdx.x == 0) {
        int t = n4 * 4 + threadIdx.x;
        if (t < n) {
            int b = (int)((x[t] - lo) * invw);
            b = min(b, NBINS_H - 1);
            b = max(b, 0);
            atomicAdd(&g_hist[b], 1u);
        }
    }
}

// ---------------------------------------------------------------------------
// K2b: collapse 256K bins -> 32K bins (sum groups of 8). Exactly equivalent
// to direct 32K binning since the grids nest: b32 = b256 >> 3.
// ---------------------------------------------------------------------------
__global__ void __launch_bounds__(256) k_collapse() {
    int b = blockIdx.x * blockDim.x + threadIdx.x;
    if (b < NBINS_S) {
        const uint4* h4 = (const uint4*)&g_hist[b * COLLAPSE];
        uint4 a = h4[0], c = h4[1];
        g_hist_s[b] = a.x + a.y + a.z + a.w + c.x + c.y + c.z + c.w;
    }
}

// ---------------------------------------------------------------------------
// K3: grid (NUM_T, NCHUNK). Block (i, c) scores candidate i+1 over bin chunk c.
// score contribution = sum_bins count * |ctr - clamp(rint(ctr/scale))*scale|^2.4
// fp32 inner loop + Kahan per thread; double block reduce; deterministic store.
// ---------------------------------------------------------------------------
__global__ void __launch_bounds__(256) k_scores() {
    const int i     = blockIdx.x + 1;
    const int chunk = blockIdx.y;

    const float xmin = dec_f(g_min_enc);
    const float xmax = dec_f(g_max_enc);
    const float xr   = fmaxf(fabsf(xmin), xmax);

    const float thres = xr / 100.0f * (float)i;          // match ref fp32 order
    const float scale = fmaxf(thres / 127.5f, 1e-8f);
    const float inv_scale = 1.0f / scale;

    const float lo = -xr;
    const float w  = 2.0f * xr / (float)NBINS_S;

    float acc = 0.0f, comp = 0.0f;                        // Kahan
    const int b_end = (chunk + 1) * BINS_PER_CHUNK;
    for (int b = chunk * BINS_PER_CHUNK + threadIdx.x; b < b_end; b += 256) {
        unsigned int cnt = g_hist_s[b];
        if (cnt == 0u) continue;
        float c = fmaf((float)b + 0.5f, w, lo);           // bin center
        float t = c * inv_scale;
        float r = rintf(t);                               // round half-even
        r = fminf(fmaxf(r, -128.0f), 127.0f);             // clip
        float e = fabsf(fmaf(-r, scale, c));              // |c - r*scale|
        float p = exp2f(2.4f * __log2f(e));               // e^2.4 (e=0 -> 0)
        float term = (float)cnt * p;
        float y = term - comp;
        float s = acc + y;
        comp = (s - acc) - y;
        acc = s;
    }

    __shared__ double sacc[256];
    sacc[threadIdx.x] = (double)acc;
    __syncthreads();
    for (int s = 128; s > 0; s >>= 1) {
        if (threadIdx.x < s) sacc[threadIdx.x] += sacc[threadIdx.x + s];
        __syncthreads();
    }
    if (threadIdx.x == 0) g_partial[blockIdx.x][chunk] = sacc[0];
}

// ---------------------------------------------------------------------------
// K4: fixed-order chunk sums, argmin (strict <, ascending i) -> output.
// ---------------------------------------------------------------------------
__global__ void k_argmin(float* __restrict__ out) {
    if (threadIdx.x == 0 && blockIdx.x == 0) {
        const float xmin = dec_f(g_min_enc);
        const float xmax = dec_f(g_max_enc);
        const float xr   = fmaxf(fabsf(xmin), xmax);

        double best = 1e300;
        int bi = 1;
        #pragma unroll 1
        for (int i = 1; i <= NUM_T; i++) {
            double s = 0.0;
            #pragma unroll
            for (int c = 0; c < NCHUNK; c++) s += g_partial[i - 1][c];
            if (s < best) { best = s; bi = i; }
        }
        float thres = xr / 100.0f * (float)bi;
        out[0] = -thres;
        out[1] =  thres;
    }
}

// ---------------------------------------------------------------------------
// Launch: 6 kernels on the default stream (graph-capturable, no allocs).
// ---------------------------------------------------------------------------
extern "C" void kernel_launch(void* const* d_in, const int* in_sizes, int n_in,
                              void* d_out, int out_size) {
    const float* x = (const float*)d_in[0];
    const int n = in_sizes[0];

    k_init<<<(NBINS_H + 255) / 256, 256>>>();
    k_minmax<<<1184, 256>>>(x, n);
    k_hist<<<1184, 256>>>(x, n);
    k_collapse<<<(NBINS_S + 255) / 256, 256>>>();
    dim3 sg(NUM_T, NCHUNK);
    k_scores<<<sg, 256>>>();
    k_argmin<<<1, 32>>>((float*)d_out);
}

// round 4
// speedup vs baseline: 2.9066x; 1.1748x over previous
#include <cuda_runtime.h>
#include <math.h>
#include <stdint.h>

// ---------------------------------------------------------------------------
// MSEObserver: 100-candidate symmetric-threshold grid search, Lp loss p=2.4.
// R4: k_hist is REDG-lane-wavefront bound (~1.29 cyc/lane). Changes:
//  - hash-interleaved bin layout (bijective odd-mult perm) to spread the hot
//    central bins across all LTS slices (kills hot-slice contention),
//  - 1-FFMA binning via magic-number rounding, no clamps (margined invw),
//  - minmax pass reduced to absmax (output only needs xrange).
// Scoring path identical in structure to the validated R3 kernel; bin centers
// adjusted to the round-based edges.
// ---------------------------------------------------------------------------

#define NBINS_H (1 << 18)                  // 262144 histogram bins (1 MB)
#define NBINS_S (1 << 15)                  // 32768 scoring bins
#define NUM_T 100
#define NCHUNK 8
#define BINS_PER_CHUNK (NBINS_S / NCHUNK)  // 4096

#define PERM_MULT 0x9E3779B1u              // odd -> bijective mod 2^18
#define PERM_MASK (NBINS_H - 1)
#define MAGIC 12582912.0f                  // 2^23 + 2^22
#define BIN_OFF 2.0f                       // low-side safety offset
#define BIN_SPAN ((float)(NBINS_H - 8))    // top-side safety margin

__device__ unsigned int g_absmax_bits;     // max|x| >= 0 -> raw-bit atomicMax ok
__device__ unsigned int g_hist[NBINS_H];
__device__ unsigned int g_hist_s[NBINS_S];
__device__ double       g_partial[NUM_T][NCHUNK];

// ---------------------------------------------------------------------------
// K0: reset all device-global scratch (graph replays must be deterministic).
// ---------------------------------------------------------------------------
__global__ void k_init() {
    int idx = blockIdx.x * blockDim.x + threadIdx.x;
    if (idx < NBINS_H) g_hist[idx] = 0u;
    if (idx == 0) g_absmax_bits = 0u;
    if (idx < NUM_T * NCHUNK) ((double*)g_partial)[idx] = 0.0;
}

// ---------------------------------------------------------------------------
// K1: absmax = max(|x|). One FMNMX(|.|)/elem; DRAM-bound.
// ---------------------------------------------------------------------------
__global__ void __launch_bounds__(256) k_absmax(const float* __restrict__ x, int n) {
    const int n4 = n >> 2;
    const float4* __restrict__ x4 = (const float4*)x;

    float m0 = 0.0f, m1 = 0.0f;
    for (int i = blockIdx.x * blockDim.x + threadIdx.x; i < n4;
         i += gridDim.x * blockDim.x) {
        float4 v = x4[i];
        m0 = fmaxf(m0, fmaxf(fabsf(v.x), fabsf(v.y)));
        m1 = fmaxf(m1, fmaxf(fabsf(v.z), fabsf(v.w)));
    }
    if (blockIdx.x == 0) {                       // tail
        int t = n4 * 4 + threadIdx.x;
        if (t < n) m0 = fmaxf(m0, fabsf(x[t]));
    }
    float m = fmaxf(m0, m1);

    for (int o = 16; o > 0; o >>= 1)
        m = fmaxf(m, __shfl_xor_sync(0xffffffffu, m, o));
    __shared__ float sm[8];
    int wid = threadIdx.x >> 5, lid = threadIdx.x & 31;
    if (lid == 0) sm[wid] = m;
    __syncthreads();
    if (wid == 0) {
        m = (lid < 8) ? sm[lid] : 0.0f;
        for (int o = 4; o > 0; o >>= 1)
            m = fmaxf(m, __shfl_xor_sync(0xffffffffu, m, o));
        if (lid == 0) atomicMax(&g_absmax_bits, __float_as_uint(m));
    }
}

// ---------------------------------------------------------------------------
// K2: hash-permuted histogram over [-xr, xr].
// bin = round((v+xr)*invw) + BIN_OFF via ONE fused FFMA + magic number,
// stored at perm(bin). invw scaled so 1 <= bin <= NBINS_H-4 structurally.
// ---------------------------------------------------------------------------
__global__ void __launch_bounds__(256) k_hist(const float* __restrict__ x, int n) {
    const float xr   = __uint_as_float(g_absmax_bits);
    const float invw = BIN_SPAN / (2.0f * xr);
    const float C    = xr * invw + (MAGIC + BIN_OFF);   // folds +xr shift, offset, magic

    const int n4 = n >> 2;
    const float4* __restrict__ x4 = (const float4*)x;

    for (int i = blockIdx.x * blockDim.x + threadIdx.x; i < n4;
         i += gridDim.x * blockDim.x) {
        float4 v = x4[i];
        float vv[4] = {v.x, v.y, v.z, v.w};
        #pragma unroll
        for (int k = 0; k < 4; k++) {
            float f = fmaf(vv[k], invw, C);               // t + magic (rn)
            unsigned int b = __float_as_uint(f) & 0x3FFFFFu;  // = round(t)+OFF
            unsigned int p = (b * PERM_MULT) & PERM_MASK;
            atomicAdd(&g_hist[p], 1u);
        }
    }
    if (blockIdx.x == 0) {                                // tail
        int t = n4 * 4 + threadIdx.x;
        if (t < n) {
            float f = fmaf(x[t], invw, C);
            unsigned int b = __float_as_uint(f) & 0x3FFFFFu;
            unsigned int p = (b * PERM_MULT) & PERM_MASK;
            atomicAdd(&g_hist[p], 1u);
        }
    }
}

// ---------------------------------------------------------------------------
// K2b: collapse 256K (permuted) bins -> 32K scoring bins. Score bin s sums
// logical hist bins [8s, 8s+8) gathered through the permutation.
// ---------------------------------------------------------------------------
__global__ void __launch_bounds__(256) k_collapse() {
    int s = blockIdx.x * blockDim.x + threadIdx.x;
    if (s < NBINS_S) {
        unsigned int base = (unsigned int)s * 8u;
        unsigned int acc = 0u;
        #pragma unroll
        for (unsigned int j = 0; j < 8; j++) {
            unsigned int p = ((base + j) * PERM_MULT) & PERM_MASK;
            acc += g_hist[p];
        }
        g_hist_s[s] = acc;
    }
}

// ---------------------------------------------------------------------------
// K3: grid (NUM_T, NCHUNK). Score candidate i+1 over chunk of scoring bins.
// Logical hist bin h covers values round((v+xr)*invw)+OFF = h, i.e. value
// center of h = (h - OFF)/invw - xr. Score bin s = hist bins [8s, 8s+8)
// -> value center c = (8s + 3.5 - OFF)*wH - xr,  wH = 1/invw.
// fp32 inner loop + Kahan; double block reduce; deterministic store.
// ---------------------------------------------------------------------------
__global__ void __launch_bounds__(256) k_scores() {
    const int i     = blockIdx.x + 1;
    const int chunk = blockIdx.y;

    const float xr   = __uint_as_float(g_absmax_bits);
    const float invw = BIN_SPAN / (2.0f * xr);
    const float wH   = 1.0f / invw;

    const float thres = xr / 100.0f * (float)i;          // match ref fp32 order
    const float scale = fmaxf(thres / 127.5f, 1e-8f);
    const float inv_scale = 1.0f / scale;

    const float c0 = (3.5f - BIN_OFF) * wH - xr;         // c = 8s*wH + c0
    const float w8 = 8.0f * wH;

    float acc = 0.0f, comp = 0.0f;                        // Kahan
    const int b_end = (chunk + 1) * BINS_PER_CHUNK;
    for (int b = chunk * BINS_PER_CHUNK + threadIdx.x; b < b_end; b += 256) {
        unsigned int cnt = g_hist_s[b];
        if (cnt == 0u) continue;
        float c = fmaf((float)b, w8, c0);                 // bin-center value
        float t = c * inv_scale;
        float r = rintf(t);                               // round half-even
        r = fminf(fmaxf(r, -128.0f), 127.0f);             // clip
        float e = fabsf(fmaf(-r, scale, c));              // |c - r*scale|
        float p = exp2f(2.4f * __log2f(e));               // e^2.4 (e=0 -> 0)
        float term = (float)cnt * p;
        float y = term - comp;
        float s = acc + y;
        comp = (s - acc) - y;
        acc = s;
    }

    __shared__ double sacc[256];
    sacc[threadIdx.x] = (double)acc;
    __syncthreads();
    for (int s = 128; s > 0; s >>= 1) {
        if (threadIdx.x < s) sacc[threadIdx.x] += sacc[threadIdx.x + s];
        __syncthreads();
    }
    if (threadIdx.x == 0) g_partial[blockIdx.x][chunk] = sacc[0];
}

// ---------------------------------------------------------------------------
// K4: fixed-order chunk sums, argmin (strict <, ascending i) -> output.
// ---------------------------------------------------------------------------
__global__ void k_argmin(float* __restrict__ out) {
    if (threadIdx.x == 0 && blockIdx.x == 0) {
        const float xr = __uint_as_float(g_absmax_bits);

        double best = 1e300;
        int bi = 1;
        #pragma unroll 1
        for (int i = 1; i <= NUM_T; i++) {
            double s = 0.0;
            #pragma unroll
            for (int c = 0; c < NCHUNK; c++) s += g_partial[i - 1][c];
            if (s < best) { best = s; bi = i; }
        }
        float thres = xr / 100.0f * (float)bi;
        out[0] = -thres;
        out[1] =  thres;
    }
}

// ---------------------------------------------------------------------------
// Launch: 6 kernels on the default stream (graph-capturable, no allocs).
// ---------------------------------------------------------------------------
extern "C" void kernel_launch(void* const* d_in, const int* in_sizes, int n_in,
                              void* d_out, int out_size) {
    const float* x = (const float*)d_in[0];
    const int n = in_sizes[0];

    k_init<<<(NBINS_H + 255) / 256, 256>>>();
    k_absmax<<<1184, 256>>>(x, n);
    k_hist<<<1184, 256>>>(x, n);
    k_collapse<<<(NBINS_S + 255) / 256, 256>>>();
    dim3 sg(NUM_T, NCHUNK);
    k_scores<<<sg, 256>>>();
    k_argmin<<<1, 32>>>((float*)d_out);
}